// round 8
// baseline (speedup 1.0000x reference)
#include <cuda_runtime.h>
#include <cuda_bf16.h>
#include <cstdint>

#define Nn  50000
#define Ee  640000
#define HIDd 128
#define Hh  8
#define EFd 16
#define Ll  3

// ---------------- scratch (static device globals; no allocations) ----------------
__device__ __align__(16) float g_xl[Nn * HIDd];
__device__ __align__(16) float g_xr[Nn * HIDd];
__device__ __align__(16) float g_M[Ll * EFd * HIDd];
__device__ __align__(16) float g_c[Ll * HIDd];
__device__ int g_deg[Nn];
__device__ int g_off[Nn + 1];
__device__ int g_cur[Nn];
__device__ int g_srcS[Ee];                       // src reordered into CSR order
__device__ __align__(16) float g_eaS[Ee * EFd];  // edge_attr reordered into CSR order
__device__ __align__(16) __nv_bfloat16 g_Wbh[2][HIDd * HIDd];  // W^T hi (bf16), [n][k]
__device__ __align__(16) __nv_bfloat16 g_Wbl[2][HIDd * HIDd];  // W^T lo (bf16), [n][k]

// ---------------- mma.sync helpers (sm_80+ instructions; no arch suffix needed) ----------------
__device__ __forceinline__ uint32_t smem_u32(const void* p) {
    uint32_t a;
    asm("{ .reg .u64 t; cvta.to.shared.u64 t, %1; cvt.u32.u64 %0, t; }" : "=r"(a) : "l"(p));
    return a;
}
__device__ __forceinline__ void ldsm_x4(uint32_t& r0, uint32_t& r1, uint32_t& r2, uint32_t& r3,
                                        uint32_t addr) {
    asm volatile("ldmatrix.sync.aligned.m8n8.x4.shared.b16 {%0,%1,%2,%3}, [%4];"
                 : "=r"(r0), "=r"(r1), "=r"(r2), "=r"(r3) : "r"(addr));
}
__device__ __forceinline__ void mma_bf16(float* c, const uint32_t* a, const uint32_t* b) {
    asm volatile(
        "mma.sync.aligned.m16n8k16.row.col.f32.bf16.bf16.f32 "
        "{%0,%1,%2,%3}, {%4,%5,%6,%7}, {%8,%9}, {%0,%1,%2,%3};"
        : "+f"(c[0]), "+f"(c[1]), "+f"(c[2]), "+f"(c[3])
        : "r"(a[0]), "r"(a[1]), "r"(a[2]), "r"(a[3]), "r"(b[0]), "r"(b[1]));
}

// smem geometry for gemm_mma (bf16 elements, padded K stride)
#define LDK 136                       // 128 + 8 pad  -> row stride 272 B (16 mod 128: conflict-free ldmatrix)
#define ABYTES (128 * LDK * 2)        // 34816
#define AH_OFF 0
#define AL_OFF ABYTES
#define BH_OFF (2 * ABYTES)
#define BL_OFF (3 * ABYTES)
#define SMEM_TOT (4 * ABYTES)         // 139264

// ---------------- small utility kernels ----------------
__global__ void copy_kernel(const float4* __restrict__ src, float4* __restrict__ dst, int n4) {
    int i = blockIdx.x * blockDim.x + threadIdx.x;
    if (i < n4) dst[i] = src[i];
}
__global__ void zero_deg_kernel(int* __restrict__ deg) {
    int i = blockIdx.x * blockDim.x + threadIdx.x;
    if (i < Nn) deg[i] = 0;
}
__global__ void hist_kernel(const int* __restrict__ dst, int* __restrict__ deg) {
    int e = blockIdx.x * blockDim.x + threadIdx.x;
    if (e < Ee) atomicAdd(&deg[dst[e]], 1);
}
__global__ void scan_kernel(const int* __restrict__ deg, int* __restrict__ off,
                            int* __restrict__ cur) {
    __shared__ int sums[1024];
    const int t = threadIdx.x;
    const int CH = 49;
    int beg = t * CH;
    int local = 0;
#pragma unroll 1
    for (int i = 0; i < CH; i++) { int idx = beg + i; if (idx < Nn) local += deg[idx]; }
    sums[t] = local;
    __syncthreads();
    int run = local;
    for (int ofs = 1; ofs < 1024; ofs <<= 1) {
        int u = (t >= ofs) ? sums[t - ofs] : 0;
        __syncthreads();
        run += u; sums[t] = run;
        __syncthreads();
    }
    int base = run - local;
#pragma unroll 1
    for (int i = 0; i < CH; i++) {
        int idx = beg + i;
        if (idx < Nn) { off[idx] = base; cur[idx] = base; base += deg[idx]; }
    }
    if (t == 0) off[Nn] = Ee;
}
__global__ void scatter_kernel(const int* __restrict__ srcArr, const int* __restrict__ dst,
                               const float* __restrict__ ea, int* __restrict__ cur,
                               int* __restrict__ srcS, float* __restrict__ eaS) {
    int e = blockIdx.x * blockDim.x + threadIdx.x;
    if (e >= Ee) return;
    int p = atomicAdd(&cur[dst[e]], 1);
    srcS[p] = srcArr[e];
    const float4* s4 = (const float4*)(ea + (size_t)e * EFd);
    float4* d4 = (float4*)(eaS + (size_t)p * EFd);
    d4[0] = s4[0]; d4[1] = s4[1]; d4[2] = s4[2]; d4[3] = s4[3];
}
__global__ void precompute_kernel(const float* __restrict__ Wt, const float* __restrict__ bt,
                                  const float* __restrict__ We,
                                  float* __restrict__ M, float* __restrict__ cv) {
    int l = blockIdx.x;
    int j = threadIdx.x;
    const float* Wel = We + l * HIDd * HIDd;
    float acc[EFd];
#pragma unroll
    for (int k = 0; k < EFd; k++) acc[k] = 0.f;
    float cacc = 0.f;
    for (int i = 0; i < HIDd; i++) {
        float w = Wel[i * HIDd + j];
        cacc = fmaf(bt[i], w, cacc);
#pragma unroll
        for (int k = 0; k < EFd; k++) acc[k] = fmaf(Wt[k * HIDd + i], w, acc[k]);
    }
#pragma unroll
    for (int k = 0; k < EFd; k++) M[l * EFd * HIDd + k * HIDd + j] = acc[k];
    cv[l * HIDd + j] = cacc;
}

// W^T split prep: Wb[n][k] = bf16 split of W[k][n]. blockIdx.y: 0=Wl, 1=Wr.
__global__ void prep_w_kernel(const float* __restrict__ W0, const float* __restrict__ W1,
                              __nv_bfloat16* __restrict__ WbhBase,
                              __nv_bfloat16* __restrict__ WblBase) {
    const float* W = blockIdx.y ? W1 : W0;
    __nv_bfloat16* Wh = WbhBase + (size_t)blockIdx.y * HIDd * HIDd;
    __nv_bfloat16* Wl = WblBase + (size_t)blockIdx.y * HIDd * HIDd;
    int n = blockIdx.x;
    int k = threadIdx.x;
    float w = W[k * HIDd + n];
    __nv_bfloat16 h = __float2bfloat16_rn(w);
    __nv_bfloat16 lo = __float2bfloat16_rn(w - __bfloat162float(h));
    Wh[n * HIDd + k] = h;
    Wl[n * HIDd + k] = lo;
}

// ---------------- tensor-core GEMM via mma.sync: C[nrows,128] = A @ W + b ----------------
// 3-term bf16 split: Ah*Wh + Ah*Wl + Al*Wh, fp32 accum. grid.y selects (W,b,C) set.
__global__ void __launch_bounds__(256) gemm_mma(const float* __restrict__ A,
                                                const __nv_bfloat16* __restrict__ Wbh0,
                                                const __nv_bfloat16* __restrict__ Wbl0,
                                                const float* __restrict__ b0, float* __restrict__ C0,
                                                const __nv_bfloat16* __restrict__ Wbh1,
                                                const __nv_bfloat16* __restrict__ Wbl1,
                                                const float* __restrict__ b1, float* __restrict__ C1,
                                                int nrows) {
    extern __shared__ char smem[];
    const __nv_bfloat16* Wbh = blockIdx.y ? Wbh1 : Wbh0;
    const __nv_bfloat16* Wbl = blockIdx.y ? Wbl1 : Wbl0;
    const float* bias = blockIdx.y ? b1 : b0;
    float* C = blockIdx.y ? C1 : C0;

    const uint32_t sb = smem_u32(smem);
    const int tid = threadIdx.x;
    const int wid = tid >> 5;
    const int lane = tid & 31;
    const int ctaRow = blockIdx.x * 128;

    // ---- prologue: A f32 -> bf16 hi/lo smem; B hi/lo smem ----
#pragma unroll
    for (int i = 0; i < 16; i++) {
        int idx = tid + i * 256;          // 0..4095 over 128 rows x 32 float4
        int row = idx >> 5;
        int c4  = idx & 31;
        int gr = ctaRow + row;
        float4 f = (gr < nrows) ? ((const float4*)A)[(size_t)gr * 32 + c4]
                                : make_float4(0.f, 0.f, 0.f, 0.f);
        __nv_bfloat162 h0 = __floats2bfloat162_rn(f.x, f.y);
        __nv_bfloat162 h1 = __floats2bfloat162_rn(f.z, f.w);
        float2 r0 = __bfloat1622float2(h0);
        float2 r1 = __bfloat1622float2(h1);
        __nv_bfloat162 l0 = __floats2bfloat162_rn(f.x - r0.x, f.y - r0.y);
        __nv_bfloat162 l1 = __floats2bfloat162_rn(f.z - r1.x, f.w - r1.y);
        uint32_t off = (uint32_t)(row * LDK + c4 * 4) * 2;
        *(uint2*)(smem + AH_OFF + off) = make_uint2(*(uint32_t*)&h0, *(uint32_t*)&h1);
        *(uint2*)(smem + AL_OFF + off) = make_uint2(*(uint32_t*)&l0, *(uint32_t*)&l1);
    }
#pragma unroll
    for (int i = 0; i < 8; i++) {
        int idx = tid + i * 256;          // 0..2047 over 128 rows x 16 uint4
        int row = idx >> 4;
        int c16 = (idx & 15) * 16;
        uint32_t off = (uint32_t)(row * (LDK * 2) + c16);
        *(uint4*)(smem + BH_OFF + off) = ((const uint4*)Wbh)[idx];
        *(uint4*)(smem + BL_OFF + off) = ((const uint4*)Wbl)[idx];
    }
    __syncthreads();

    // ---- main mma loops ----
    const int warpRow = wid >> 1;   // 0..3 -> M offset *32
    const int warpCol = wid & 1;    // 0..1 -> N offset *64

    float acc[2][8][4];
#pragma unroll
    for (int mt = 0; mt < 2; mt++)
#pragma unroll
        for (int nt = 0; nt < 8; nt++)
#pragma unroll
            for (int q = 0; q < 4; q++) acc[mt][nt][q] = 0.f;

    const int aRow   = warpRow * 32 + (lane & 15);
    const int aKhalf = (lane >> 4) * 8;
    const int bRow   = warpCol * 64 + ((lane >> 4) << 3) + (lane & 7);
    const int bKhalf = ((lane >> 3) & 1) * 8;

#pragma unroll
    for (int term = 0; term < 3; term++) {
        const uint32_t aBase = sb + ((term == 2) ? AL_OFF : AH_OFF);
        const uint32_t bBase = sb + ((term == 1) ? BL_OFF : BH_OFF);
#pragma unroll
        for (int kk = 0; kk < 8; kk++) {
            const int k0 = kk * 16;
            uint32_t a0[4], a1[4];
            ldsm_x4(a0[0], a0[1], a0[2], a0[3],
                    aBase + (uint32_t)((aRow)      * LDK + k0 + aKhalf) * 2);
            ldsm_x4(a1[0], a1[1], a1[2], a1[3],
                    aBase + (uint32_t)((aRow + 16) * LDK + k0 + aKhalf) * 2);
            uint32_t b[8][2];
#pragma unroll
            for (int p = 0; p < 4; p++) {
                uint32_t r0, r1, r2, r3;
                ldsm_x4(r0, r1, r2, r3,
                        bBase + (uint32_t)((bRow + p * 16) * LDK + k0 + bKhalf) * 2);
                b[p * 2 + 0][0] = r0; b[p * 2 + 0][1] = r1;
                b[p * 2 + 1][0] = r2; b[p * 2 + 1][1] = r3;
            }
#pragma unroll
            for (int nt = 0; nt < 8; nt++) {
                mma_bf16(acc[0][nt], a0, b[nt]);
                mma_bf16(acc[1][nt], a1, b[nt]);
            }
        }
    }

    // ---- epilogue: +bias, store ----
#pragma unroll
    for (int mt = 0; mt < 2; mt++) {
        int r0 = ctaRow + warpRow * 32 + mt * 16 + (lane >> 2);
        int r1 = r0 + 8;
#pragma unroll
        for (int nt = 0; nt < 8; nt++) {
            int col = warpCol * 64 + nt * 8 + (lane & 3) * 2;
            float2 bv = *(const float2*)(bias + col);
            if (r0 < nrows) {
                float2 o; o.x = acc[mt][nt][0] + bv.x; o.y = acc[mt][nt][1] + bv.y;
                *(float2*)(C + (size_t)r0 * HIDd + col) = o;
            }
            if (r1 < nrows) {
                float2 o; o.x = acc[mt][nt][2] + bv.x; o.y = acc[mt][nt][3] + bv.y;
                *(float2*)(C + (size_t)r1 * HIDd + col) = o;
            }
        }
    }
}

// ---------------- fused node pass (R4 version, best known) ----------------
__global__ void __launch_bounds__(256) node_kernel(const float* __restrict__ eaS,
                                                   const int* __restrict__ srcS,
                                                   const float* __restrict__ xl,
                                                   const float* __restrict__ xr,
                                                   const int* __restrict__ off,
                                                   const float* __restrict__ M,
                                                   const float* __restrict__ cvec,
                                                   const float* __restrict__ att,
                                                   const float* __restrict__ bias_o,
                                                   const float* __restrict__ lng,
                                                   const float* __restrict__ lnb,
                                                   float* __restrict__ x) {
    __shared__ __align__(16) float sM[EFd * HIDd];
    __shared__ __align__(16) float sC[HIDd];
    __shared__ __align__(16) float sA[HIDd];
    const int tid = threadIdx.x;
    for (int i = tid; i < EFd * HIDd; i += 256) sM[i] = M[i];
    if (tid < HIDd) {
        sC[tid] = cvec[tid];
        sA[tid] = att[tid] * 1.4426950408889634f;
    }
    __syncthreads();

    const int n = (blockIdx.x * 256 + tid) >> 5;
    const int lane = tid & 31;
    if (n >= Nn) return;

    const int beg = off[n];
    const int end = off[n + 1];

    const float4 xrv = ((const float4*)xr)[(size_t)n * 32 + lane];
    const float4 cv4 = ((const float4*)sC)[lane];
    const float4 av  = ((const float4*)sA)[lane];
    const float4* sM4 = (const float4*)sM;

    float4 acc = make_float4(0.f, 0.f, 0.f, 0.f);
    float dsum = 0.f;

    float  eav0 = 0.f;
    float4 xlv0 = make_float4(0.f, 0.f, 0.f, 0.f);
    if (beg < end) {
        eav0 = eaS[(size_t)beg * EFd + (lane & 15)];
        int s0 = srcS[beg];
        xlv0 = ((const float4*)xl)[(size_t)s0 * 32 + lane];
    }

    for (int i = beg; i < end; i++) {
        float  eav1 = eav0;
        float4 xlv1 = xlv0;
        if (i + 1 < end) {
            eav1 = eaS[(size_t)(i + 1) * EFd + (lane & 15)];
            int s1 = srcS[i + 1];
            xlv1 = ((const float4*)xl)[(size_t)s1 * 32 + lane];
        }
        const float  eav = eav0;
        const float4 xlv = xlv0;

        float4 emA = cv4;
        float4 emB = make_float4(0.f, 0.f, 0.f, 0.f);
#pragma unroll
        for (int k = 0; k < 8; k++) {
            float a = __shfl_sync(0xffffffffu, eav, k);
            float4 mv = sM4[k * 32 + lane];
            emA.x = fmaf(a, mv.x, emA.x);
            emA.y = fmaf(a, mv.y, emA.y);
            emA.z = fmaf(a, mv.z, emA.z);
            emA.w = fmaf(a, mv.w, emA.w);
        }
#pragma unroll
        for (int k = 8; k < 16; k++) {
            float a = __shfl_sync(0xffffffffu, eav, k);
            float4 mv = sM4[k * 32 + lane];
            emB.x = fmaf(a, mv.x, emB.x);
            emB.y = fmaf(a, mv.y, emB.y);
            emB.z = fmaf(a, mv.z, emB.z);
            emB.w = fmaf(a, mv.w, emB.w);
        }
        float4 m;
        m.x = xlv.x + xrv.x + emA.x + emB.x;
        m.y = xlv.y + xrv.y + emA.y + emB.y;
        m.z = xlv.z + xrv.z + emA.z + emB.z;
        m.w = xlv.w + xrv.w + emA.w + emB.w;
        m.x = (m.x > 0.f) ? m.x : 0.2f * m.x;
        m.y = (m.y > 0.f) ? m.y : 0.2f * m.y;
        m.z = (m.z > 0.f) ? m.z : 0.2f * m.z;
        m.w = (m.w > 0.f) ? m.w : 0.2f * m.w;

        float part = m.x * av.x + m.y * av.y + m.z * av.z + m.w * av.w;
        part += __shfl_xor_sync(0xffffffffu, part, 1);
        part += __shfl_xor_sync(0xffffffffu, part, 2);

        float p = exp2f(part);
        dsum += p;
        acc.x = fmaf(p, xlv.x, acc.x);
        acc.y = fmaf(p, xlv.y, acc.y);
        acc.z = fmaf(p, xlv.z, acc.z);
        acc.w = fmaf(p, xlv.w, acc.w);

        eav0 = eav1;
        xlv0 = xlv1;
    }

    const float inv = 1.0f / (dsum + 1e-16f);
    float4 bo = ((const float4*)bias_o)[lane];
    float4 o;
    o.x = acc.x * inv + bo.x;
    o.y = acc.y * inv + bo.y;
    o.z = acc.z * inv + bo.z;
    o.w = acc.w * inv + bo.w;

    float s  = o.x + o.y + o.z + o.w;
    float sq = o.x * o.x + o.y * o.y + o.z * o.z + o.w * o.w;
#pragma unroll
    for (int ofs = 16; ofs > 0; ofs >>= 1) {
        s  += __shfl_xor_sync(0xffffffffu, s, ofs);
        sq += __shfl_xor_sync(0xffffffffu, sq, ofs);
    }
    float mu   = s * (1.0f / 128.0f);
    float var  = sq * (1.0f / 128.0f) - mu * mu;
    float rstd = rsqrtf(var + 1e-5f);

    float4 gv = ((const float4*)lng)[lane];
    float4 bv = ((const float4*)lnb)[lane];
    float4 xv = ((float4*)x)[(size_t)n * 32 + lane];
    float y;
    y = gv.x * (o.x - mu) * rstd + bv.x; xv.x += fmaxf(y, 0.f);
    y = gv.y * (o.y - mu) * rstd + bv.y; xv.y += fmaxf(y, 0.f);
    y = gv.z * (o.z - mu) * rstd + bv.z; xv.z += fmaxf(y, 0.f);
    y = gv.w * (o.w - mu) * rstd + bv.w; xv.w += fmaxf(y, 0.f);
    ((float4*)x)[(size_t)n * 32 + lane] = xv;
}

// ---------------- launch ----------------
extern "C" void kernel_launch(void* const* d_in, const int* in_sizes, int n_in,
                              void* d_out, int out_size) {
    const float* x   = (const float*)d_in[0];
    const int*   ei  = (const int*)d_in[2];
    const float* ea  = (const float*)d_in[3];
    const float* Wt  = (const float*)d_in[4];
    const float* bt  = (const float*)d_in[5];
    const float* Wl  = (const float*)d_in[6];
    const float* bl  = (const float*)d_in[7];
    const float* Wr  = (const float*)d_in[8];
    const float* br  = (const float*)d_in[9];
    const float* We  = (const float*)d_in[10];
    const float* att = (const float*)d_in[11];
    const float* bo  = (const float*)d_in[12];
    const float* lg  = (const float*)d_in[13];
    const float* lb  = (const float*)d_in[14];
    float* xbuf = (float*)d_out;

    float *pxl, *pxr, *pM, *pc, *peaS;
    int *pdeg, *poff, *pcur, *psrcS;
    __nv_bfloat16 *pWbh, *pWbl;
    cudaGetSymbolAddress((void**)&pxl,   g_xl);
    cudaGetSymbolAddress((void**)&pxr,   g_xr);
    cudaGetSymbolAddress((void**)&pM,    g_M);
    cudaGetSymbolAddress((void**)&pc,    g_c);
    cudaGetSymbolAddress((void**)&pdeg,  g_deg);
    cudaGetSymbolAddress((void**)&poff,  g_off);
    cudaGetSymbolAddress((void**)&pcur,  g_cur);
    cudaGetSymbolAddress((void**)&psrcS, g_srcS);
    cudaGetSymbolAddress((void**)&peaS,  g_eaS);
    cudaGetSymbolAddress((void**)&pWbh,  g_Wbh);
    cudaGetSymbolAddress((void**)&pWbl,  g_Wbl);

    cudaFuncSetAttribute(gemm_mma, cudaFuncAttributeMaxDynamicSharedMemorySize, SMEM_TOT);

    const int* srcArr = ei;
    const int* dstArr = ei + Ee;
    const int n4x = Nn * 32;

    copy_kernel<<<(n4x + 255) / 256, 256>>>((const float4*)x, (float4*)xbuf, n4x);
    precompute_kernel<<<Ll, HIDd>>>(Wt, bt, We, pM, pc);

    zero_deg_kernel<<<(Nn + 255) / 256, 256>>>(pdeg);
    hist_kernel<<<(Ee + 255) / 256, 256>>>(dstArr, pdeg);
    scan_kernel<<<1, 1024>>>(pdeg, poff, pcur);
    scatter_kernel<<<(Ee + 255) / 256, 256>>>(srcArr, dstArr, ea, pcur, psrcS, peaS);

    dim3 pgrid(HIDd, 2);
    dim3 ggrid((Nn + 127) / 128, 2);
    for (int l = 0; l < Ll; l++) {
        prep_w_kernel<<<pgrid, HIDd>>>(Wl + (size_t)l * HIDd * HIDd,
                                       Wr + (size_t)l * HIDd * HIDd, pWbh, pWbl);
        gemm_mma<<<ggrid, 256, SMEM_TOT>>>(xbuf,
                                           pWbh, pWbl, bl + l * HIDd, pxl,
                                           pWbh + HIDd * HIDd, pWbl + HIDd * HIDd,
                                           br + l * HIDd, pxr, Nn);
        node_kernel<<<(Nn * 32 + 255) / 256, 256>>>(peaS, psrcS, pxl, pxr, poff,
                                                    pM + (size_t)l * EFd * HIDd, pc + l * HIDd,
                                                    att + l * HIDd, bo + l * HIDd,
                                                    lg + l * HIDd, lb + l * HIDd, xbuf);
    }
}

// round 9
// speedup vs baseline: 1.5345x; 1.5345x over previous
#include <cuda_runtime.h>
#include <cuda_bf16.h>
#include <cstdint>

#define Nn  50000
#define Ee  640000
#define HIDd 128
#define Hh  8
#define EFd 16
#define Ll  3
#define NODE_BLOCKS 782
#define NODE_WARPS (NODE_BLOCKS * 8)

typedef unsigned long long u64;

// ---------------- scratch (static device globals; no allocations) ----------------
__device__ __align__(16) float g_xl[Nn * HIDd];
__device__ __align__(16) float g_xr[Nn * HIDd];
__device__ __align__(16) float g_M[Ll * EFd * HIDd];
__device__ __align__(16) float g_c[Ll * HIDd];
__device__ int g_deg[Nn];
__device__ int g_off[Nn + 1];
__device__ int g_cur[Nn];
__device__ int g_srcS[Ee];                       // src reordered into CSR order
__device__ __align__(16) float g_eaS[Ee * EFd];  // edge_attr reordered into CSR order

// ---------------- f32x2 helpers ----------------
__device__ __forceinline__ u64 pk2(float a, float b) {
    u64 r; asm("mov.b64 %0, {%1, %2};" : "=l"(r) : "f"(a), "f"(b)); return r;
}
__device__ __forceinline__ void upk2(float& a, float& b, u64 v) {
    asm("mov.b64 {%0, %1}, %2;" : "=f"(a), "=f"(b) : "l"(v));
}
__device__ __forceinline__ u64 fma2(u64 a, u64 b, u64 c) {
    u64 d; asm("fma.rn.f32x2 %0, %1, %2, %3;" : "=l"(d) : "l"(a), "l"(b), "l"(c)); return d;
}
__device__ __forceinline__ float ex2(float x) {
    float y; asm("ex2.approx.ftz.f32 %0, %1;" : "=f"(y) : "f"(x)); return y;
}

// ---------------- small utility kernels ----------------
__global__ void copy_kernel(const float4* __restrict__ src, float4* __restrict__ dst, int n4) {
    int i = blockIdx.x * blockDim.x + threadIdx.x;
    if (i < n4) dst[i] = src[i];
}
__global__ void zero_deg_kernel(int* __restrict__ deg) {
    int i = blockIdx.x * blockDim.x + threadIdx.x;
    if (i < Nn) deg[i] = 0;
}
__global__ void hist_kernel(const int* __restrict__ dst, int* __restrict__ deg) {
    int e = blockIdx.x * blockDim.x + threadIdx.x;
    if (e < Ee) atomicAdd(&deg[dst[e]], 1);
}
__global__ void scan_kernel(const int* __restrict__ deg, int* __restrict__ off,
                            int* __restrict__ cur) {
    __shared__ int sums[1024];
    const int t = threadIdx.x;
    const int CH = 49;
    int beg = t * CH;
    int local = 0;
#pragma unroll 1
    for (int i = 0; i < CH; i++) { int idx = beg + i; if (idx < Nn) local += deg[idx]; }
    sums[t] = local;
    __syncthreads();
    int run = local;
    for (int ofs = 1; ofs < 1024; ofs <<= 1) {
        int u = (t >= ofs) ? sums[t - ofs] : 0;
        __syncthreads();
        run += u; sums[t] = run;
        __syncthreads();
    }
    int base = run - local;
#pragma unroll 1
    for (int i = 0; i < CH; i++) {
        int idx = beg + i;
        if (idx < Nn) { off[idx] = base; cur[idx] = base; base += deg[idx]; }
    }
    if (t == 0) off[Nn] = Ee;
}
__global__ void scatter_kernel(const int* __restrict__ srcArr, const int* __restrict__ dst,
                               const float* __restrict__ ea, int* __restrict__ cur,
                               int* __restrict__ srcS, float* __restrict__ eaS) {
    int e = blockIdx.x * blockDim.x + threadIdx.x;
    if (e >= Ee) return;
    int p = atomicAdd(&cur[dst[e]], 1);
    srcS[p] = srcArr[e];
    const float4* s4 = (const float4*)(ea + (size_t)e * EFd);
    float4* d4 = (float4*)(eaS + (size_t)p * EFd);
    d4[0] = s4[0]; d4[1] = s4[1]; d4[2] = s4[2]; d4[3] = s4[3];
}
__global__ void precompute_kernel(const float* __restrict__ Wt, const float* __restrict__ bt,
                                  const float* __restrict__ We,
                                  float* __restrict__ M, float* __restrict__ cv) {
    int l = blockIdx.x;
    int j = threadIdx.x;
    const float* Wel = We + l * HIDd * HIDd;
    float acc[EFd];
#pragma unroll
    for (int k = 0; k < EFd; k++) acc[k] = 0.f;
    float cacc = 0.f;
    for (int i = 0; i < HIDd; i++) {
        float w = Wel[i * HIDd + j];
        cacc = fmaf(bt[i], w, cacc);
#pragma unroll
        for (int k = 0; k < EFd; k++) acc[k] = fmaf(Wt[k * HIDd + i], w, acc[k]);
    }
#pragma unroll
    for (int k = 0; k < EFd; k++) M[l * EFd * HIDd + k * HIDd + j] = acc[k];
    cv[l * HIDd + j] = cacc;
}

// ---------------- SGEMM (R4 version, measured 59.5us/launch) ----------------
__global__ void __launch_bounds__(256, 2) gemm128x2(const float* __restrict__ A,
                                                    const float* __restrict__ W0,
                                                    const float* __restrict__ b0,
                                                    float* __restrict__ C0,
                                                    const float* __restrict__ W1,
                                                    const float* __restrict__ b1,
                                                    float* __restrict__ C1,
                                                    int nrows) {
    const float* W    = blockIdx.y ? W1 : W0;
    const float* bias = blockIdx.y ? b1 : b0;
    float*       C    = blockIdx.y ? C1 : C0;

    __shared__ __align__(16) float As[32][132];
    __shared__ __align__(16) float Bs[32][128];
    const int tid = threadIdx.x;
    const int tn = (tid & 15) * 8;
    const int tm = (tid >> 4) * 8;
    const int rowBase = blockIdx.x * 128;

    float acc[8][8];
#pragma unroll
    for (int i = 0; i < 8; i++)
#pragma unroll
        for (int j = 0; j < 8; j++) acc[i][j] = 0.f;

    const int ar = tid >> 3;
    const int ak = (tid & 7) << 2;
    const int bk = tid >> 5;
    const int bn = (tid & 31) << 2;

    for (int kc = 0; kc < 128; kc += 32) {
#pragma unroll
        for (int q = 0; q < 4; q++) {
            int r = ar + q * 32;
            int gr = rowBase + r;
            float4 v = make_float4(0.f, 0.f, 0.f, 0.f);
            if (gr < nrows) v = *(const float4*)(A + (size_t)gr * HIDd + kc + ak);
            As[ak + 0][r] = v.x; As[ak + 1][r] = v.y;
            As[ak + 2][r] = v.z; As[ak + 3][r] = v.w;
        }
#pragma unroll
        for (int q = 0; q < 4; q++) {
            int r = bk + q * 8;
            *(float4*)&Bs[r][bn] = *(const float4*)(W + (size_t)(kc + r) * HIDd + bn);
        }
        __syncthreads();
#pragma unroll
        for (int kk = 0; kk < 32; kk++) {
            float a[8], b[8];
            *(float4*)(a)     = *(const float4*)&As[kk][tm];
            *(float4*)(a + 4) = *(const float4*)&As[kk][tm + 4];
            *(float4*)(b)     = *(const float4*)&Bs[kk][tn];
            *(float4*)(b + 4) = *(const float4*)&Bs[kk][tn + 4];
#pragma unroll
            for (int i = 0; i < 8; i++)
#pragma unroll
                for (int j = 0; j < 8; j++) acc[i][j] = fmaf(a[i], b[j], acc[i][j]);
        }
        __syncthreads();
    }

    float bb[8];
#pragma unroll
    for (int j = 0; j < 8; j++) bb[j] = bias[tn + j];
#pragma unroll
    for (int i = 0; i < 8; i++) {
        int gr = rowBase + tm + i;
        if (gr < nrows) {
            float4 o;
            o.x = acc[i][0] + bb[0]; o.y = acc[i][1] + bb[1];
            o.z = acc[i][2] + bb[2]; o.w = acc[i][3] + bb[3];
            *(float4*)(C + (size_t)gr * HIDd + tn) = o;
            o.x = acc[i][4] + bb[4]; o.y = acc[i][5] + bb[5];
            o.z = acc[i][6] + bb[6]; o.w = acc[i][7] + bb[7];
            *(float4*)(C + (size_t)gr * HIDd + tn + 4) = o;
        }
    }
}

// ---------------- fused node pass: M in registers, multi-node per warp, no smem ----------------
__global__ void __launch_bounds__(256) node_kernel(const float* __restrict__ eaS,
                                                   const int* __restrict__ srcS,
                                                   const float* __restrict__ xl,
                                                   const float* __restrict__ xr,
                                                   const int* __restrict__ off,
                                                   const float* __restrict__ M,
                                                   const float* __restrict__ cvec,
                                                   const float* __restrict__ att,
                                                   const float* __restrict__ bias_o,
                                                   const float* __restrict__ lng,
                                                   const float* __restrict__ lnb,
                                                   float* __restrict__ x) {
    const int tid = threadIdx.x;
    const int lane = tid & 31;
    const int warpId = (blockIdx.x * 256 + tid) >> 5;

    // per-lane M slice: rows k=0..15, channels lane*4..lane*4+3, as 2 packed f32 pairs.
    // Loaded ONCE per warp; amortized over ~8 nodes.
    ulonglong2 Mk[EFd];
    {
        const ulonglong2* M2 = (const ulonglong2*)M;
#pragma unroll
        for (int k = 0; k < EFd; k++) Mk[k] = M2[k * 32 + lane];
    }
    const float4 cv4 = ((const float4*)cvec)[lane];
    float4 av = ((const float4*)att)[lane];
    const float L2E = 1.4426950408889634f;  // exp(x) = exp2(x*log2e)
    av.x *= L2E; av.y *= L2E; av.z *= L2E; av.w *= L2E;

    for (int n = warpId; n < Nn; n += NODE_WARPS) {
        const int beg = off[n];
        const int end = off[n + 1];

        const float4 xrv = ((const float4*)xr)[(size_t)n * 32 + lane];
        float4 pre;
        pre.x = xrv.x + cv4.x; pre.y = xrv.y + cv4.y;
        pre.z = xrv.z + cv4.z; pre.w = xrv.w + cv4.w;

        float4 acc = make_float4(0.f, 0.f, 0.f, 0.f);
        float dsum = 0.f;

        float  eav0 = 0.f;
        float4 xlv0 = make_float4(0.f, 0.f, 0.f, 0.f);
        if (beg < end) {
            eav0 = eaS[(size_t)beg * EFd + (lane & 15)];
            int s0 = srcS[beg];
            xlv0 = ((const float4*)xl)[(size_t)s0 * 32 + lane];
        }

        for (int i = beg; i < end; i++) {
            float  eav1 = eav0;
            float4 xlv1 = xlv0;
            if (i + 1 < end) {
                eav1 = eaS[(size_t)(i + 1) * EFd + (lane & 15)];
                int s1 = srcS[i + 1];
                xlv1 = ((const float4*)xl)[(size_t)s1 * 32 + lane];
            }
            const float  eav = eav0;
            const float4 xlv = xlv0;

            // em = ea(16) @ M(16x128) for this lane's 4 channels, packed f32x2
            u64 em01 = 0, em23 = 0;
#pragma unroll
            for (int k = 0; k < EFd; k++) {
                float a = __shfl_sync(0xffffffffu, eav, k);
                u64 aa = pk2(a, a);
                em01 = fma2(aa, Mk[k].x, em01);
                em23 = fma2(aa, Mk[k].y, em23);
            }
            float e0, e1, e2, e3;
            upk2(e0, e1, em01);
            upk2(e2, e3, em23);

            float m0 = xlv.x + pre.x + e0;
            float m1 = xlv.y + pre.y + e1;
            float m2 = xlv.z + pre.z + e2;
            float m3 = xlv.w + pre.w + e3;
            m0 = fmaxf(m0, 0.2f * m0);
            m1 = fmaxf(m1, 0.2f * m1);
            m2 = fmaxf(m2, 0.2f * m2);
            m3 = fmaxf(m3, 0.2f * m3);

            float part = m0 * av.x + m1 * av.y + m2 * av.z + m3 * av.w;
            part += __shfl_xor_sync(0xffffffffu, part, 1);
            part += __shfl_xor_sync(0xffffffffu, part, 2);  // logit*log2e for head = lane>>2

            float p = ex2(part);
            dsum += p;
            acc.x = fmaf(p, xlv.x, acc.x);
            acc.y = fmaf(p, xlv.y, acc.y);
            acc.z = fmaf(p, xlv.z, acc.z);
            acc.w = fmaf(p, xlv.w, acc.w);

            eav0 = eav1;
            xlv0 = xlv1;
        }

        const float inv = 1.0f / (dsum + 1e-16f);
        float4 bo = ((const float4*)bias_o)[lane];
        float4 o;
        o.x = acc.x * inv + bo.x;
        o.y = acc.y * inv + bo.y;
        o.z = acc.z * inv + bo.z;
        o.w = acc.w * inv + bo.w;

        float s  = o.x + o.y + o.z + o.w;
        float sq = o.x * o.x + o.y * o.y + o.z * o.z + o.w * o.w;
#pragma unroll
        for (int ofs = 16; ofs > 0; ofs >>= 1) {
            s  += __shfl_xor_sync(0xffffffffu, s, ofs);
            sq += __shfl_xor_sync(0xffffffffu, sq, ofs);
        }
        float mu   = s * (1.0f / 128.0f);
        float var  = sq * (1.0f / 128.0f) - mu * mu;
        float rstd = rsqrtf(var + 1e-5f);

        float4 gv = ((const float4*)lng)[lane];
        float4 bv = ((const float4*)lnb)[lane];
        float4 xv = ((float4*)x)[(size_t)n * 32 + lane];
        float y;
        y = gv.x * (o.x - mu) * rstd + bv.x; xv.x += fmaxf(y, 0.f);
        y = gv.y * (o.y - mu) * rstd + bv.y; xv.y += fmaxf(y, 0.f);
        y = gv.z * (o.z - mu) * rstd + bv.z; xv.z += fmaxf(y, 0.f);
        y = gv.w * (o.w - mu) * rstd + bv.w; xv.w += fmaxf(y, 0.f);
        ((float4*)x)[(size_t)n * 32 + lane] = xv;
    }
}

// ---------------- launch ----------------
extern "C" void kernel_launch(void* const* d_in, const int* in_sizes, int n_in,
                              void* d_out, int out_size) {
    const float* x   = (const float*)d_in[0];
    const int*   ei  = (const int*)d_in[2];
    const float* ea  = (const float*)d_in[3];
    const float* Wt  = (const float*)d_in[4];
    const float* bt  = (const float*)d_in[5];
    const float* Wl  = (const float*)d_in[6];
    const float* bl  = (const float*)d_in[7];
    const float* Wr  = (const float*)d_in[8];
    const float* br  = (const float*)d_in[9];
    const float* We  = (const float*)d_in[10];
    const float* att = (const float*)d_in[11];
    const float* bo  = (const float*)d_in[12];
    const float* lg  = (const float*)d_in[13];
    const float* lb  = (const float*)d_in[14];
    float* xbuf = (float*)d_out;

    float *pxl, *pxr, *pM, *pc, *peaS;
    int *pdeg, *poff, *pcur, *psrcS;
    cudaGetSymbolAddress((void**)&pxl,   g_xl);
    cudaGetSymbolAddress((void**)&pxr,   g_xr);
    cudaGetSymbolAddress((void**)&pM,    g_M);
    cudaGetSymbolAddress((void**)&pc,    g_c);
    cudaGetSymbolAddress((void**)&pdeg,  g_deg);
    cudaGetSymbolAddress((void**)&poff,  g_off);
    cudaGetSymbolAddress((void**)&pcur,  g_cur);
    cudaGetSymbolAddress((void**)&psrcS, g_srcS);
    cudaGetSymbolAddress((void**)&peaS,  g_eaS);

    const int* srcArr = ei;
    const int* dstArr = ei + Ee;
    const int n4x = Nn * 32;

    copy_kernel<<<(n4x + 255) / 256, 256>>>((const float4*)x, (float4*)xbuf, n4x);
    precompute_kernel<<<Ll, HIDd>>>(Wt, bt, We, pM, pc);

    zero_deg_kernel<<<(Nn + 255) / 256, 256>>>(pdeg);
    hist_kernel<<<(Ee + 255) / 256, 256>>>(dstArr, pdeg);
    scan_kernel<<<1, 1024>>>(pdeg, poff, pcur);
    scatter_kernel<<<(Ee + 255) / 256, 256>>>(srcArr, dstArr, ea, pcur, psrcS, peaS);

    dim3 ggrid((Nn + 127) / 128, 2);
    for (int l = 0; l < Ll; l++) {
        gemm128x2<<<ggrid, 256>>>(xbuf,
                                  Wl + (size_t)l * HIDd * HIDd, bl + l * HIDd, pxl,
                                  Wr + (size_t)l * HIDd * HIDd, br + l * HIDd, pxr, Nn);
        node_kernel<<<NODE_BLOCKS, 256>>>(peaS, psrcS, pxl, pxr, poff,
                                          pM + (size_t)l * EFd * HIDd, pc + l * HIDd,
                                          att + l * HIDd, bo + l * HIDd,
                                          lg + l * HIDd, lb + l * HIDd, xbuf);
    }
}